// round 1
// baseline (speedup 1.0000x reference)
#include <cuda_runtime.h>

// Problem dims (fixed by the dataset)
#define DB 32
#define DT 32
#define DK 196
#define DH 512
#define DA 512

#define OUT_ALPHA_OFF (DB*DT*DH)            // 524288
#define OUT_BETA_OFF  (DB*DT*DH + DB*DT*DK) // 724992

// Scratch (allocation-free rule: __device__ globals)
__device__ float g_cv[DB*DK*DA];   // att_feats @ Wv   (6272 x 512)
__device__ float g_cg[DB*DT*DA];   // hiddens   @ Wg   (1024 x 512)
__device__ float g_cs[DB*DT*DA];   // sentinel  @ Ws   (1024 x 512)
__device__ float g_zt[DB*DT*DK];   // logits           (1024 x 196)

// ---------------------------------------------------------------------------
// FFMA2 helpers (packed fp32x2 — 2x FFMA pipe throughput on sm_103a)
// ---------------------------------------------------------------------------
__device__ __forceinline__ void fma2(unsigned long long& c,
                                     unsigned long long a,
                                     unsigned long long b) {
    asm("fma.rn.f32x2 %0, %1, %2, %0;" : "+l"(c) : "l"(a), "l"(b));
}
__device__ __forceinline__ unsigned long long dup2(float s) {
    unsigned long long d;
    asm("mov.b64 %0, {%1, %1};" : "=l"(d) : "r"(__float_as_uint(s)));
    return d;
}
__device__ __forceinline__ float tanh_approx(float x) {
    float y;
    asm("tanh.approx.f32 %0, %1;" : "=f"(y) : "f"(x));
    return y;
}

// ---------------------------------------------------------------------------
// GEMM: C[M,512] = A[M,512] @ W[512,512], fp32, f32x2 accumulation pairs.
// BM=128, BN=64, BK=8, 256 threads, per-thread 8(M)x4(N) via 4 M-pairs.
// OUTSEL selects destination scratch buffer at compile time.
// ---------------------------------------------------------------------------
template<int OUTSEL>
__global__ __launch_bounds__(256)
void gemm_k(const float* __restrict__ Am, const float* __restrict__ Wm) {
    float* Cm = (OUTSEL == 0) ? g_cv : ((OUTSEL == 1) ? g_cg : g_cs);

    __shared__ __align__(16) float As[8][128];  // [k][m] (transposed)
    __shared__ __align__(16) float Bs[8][64];   // [k][n]

    const int tid = threadIdx.x;
    const int tx  = tid & 15;        // n direction (4 cols each)
    const int ty  = tid >> 4;        // m direction (8 rows each)
    const int m0  = blockIdx.y * 128;
    const int n0  = blockIdx.x * 64;

    // A tile load mapping: 128 rows x 8 cols, 2 threads/row, float4 each
    const int arow = tid >> 1;
    const int acol = (tid & 1) * 4;
    // B tile load mapping: 8 rows x 64 cols, 32 threads/row, float2 each
    const int brow = tid >> 5;
    const int bcol = (tid & 31) * 2;

    const float* Ap = Am + (m0 + arow) * 512 + acol;
    const float* Bp = Wm + brow * 512 + n0 + bcol;

    unsigned long long acc[4][4];   // [m-pair][n]; each holds (m_even, m_odd)
#pragma unroll
    for (int i = 0; i < 4; i++)
#pragma unroll
        for (int j = 0; j < 4; j++) acc[i][j] = 0ull;

    float4 av = *(const float4*)(Ap);
    float2 bv = *(const float2*)(Bp);

    for (int k0 = 0; k0 < 512; k0 += 8) {
        As[acol + 0][arow] = av.x;
        As[acol + 1][arow] = av.y;
        As[acol + 2][arow] = av.z;
        As[acol + 3][arow] = av.w;
        *(float2*)&Bs[brow][bcol] = bv;
        __syncthreads();

        if (k0 + 8 < 512) {  // software prefetch next tiles into registers
            av = *(const float4*)(Ap + k0 + 8);
            bv = *(const float2*)(Bp + (k0 + 8) * 512);
        }

#pragma unroll
        for (int kk = 0; kk < 8; kk++) {
            // A pairs straight from smem as 64-bit lanes (no packing needed)
            ulonglong2 aA = *(const ulonglong2*)&As[kk][ty * 8];
            ulonglong2 aB = *(const ulonglong2*)&As[kk][ty * 8 + 4];
            float4 bq = *(const float4*)&Bs[kk][tx * 4];
            unsigned long long bd0 = dup2(bq.x);
            unsigned long long bd1 = dup2(bq.y);
            unsigned long long bd2 = dup2(bq.z);
            unsigned long long bd3 = dup2(bq.w);
            fma2(acc[0][0], aA.x, bd0); fma2(acc[0][1], aA.x, bd1);
            fma2(acc[0][2], aA.x, bd2); fma2(acc[0][3], aA.x, bd3);
            fma2(acc[1][0], aA.y, bd0); fma2(acc[1][1], aA.y, bd1);
            fma2(acc[1][2], aA.y, bd2); fma2(acc[1][3], aA.y, bd3);
            fma2(acc[2][0], aB.x, bd0); fma2(acc[2][1], aB.x, bd1);
            fma2(acc[2][2], aB.x, bd2); fma2(acc[2][3], aB.x, bd3);
            fma2(acc[3][0], aB.y, bd0); fma2(acc[3][1], aB.y, bd1);
            fma2(acc[3][2], aB.y, bd2); fma2(acc[3][3], aB.y, bd3);
        }
        __syncthreads();
    }

#pragma unroll
    for (int mp = 0; mp < 4; mp++) {
        float2 v0 = *(float2*)&acc[mp][0];
        float2 v1 = *(float2*)&acc[mp][1];
        float2 v2 = *(float2*)&acc[mp][2];
        float2 v3 = *(float2*)&acc[mp][3];
        const int m = m0 + ty * 8 + mp * 2;
        float* crow = Cm + m * 512 + n0 + tx * 4;
        float4 e0 = make_float4(v0.x, v1.x, v2.x, v3.x);
        float4 e1 = make_float4(v0.y, v1.y, v2.y, v3.y);
        *(float4*)(crow)       = e0;
        *(float4*)(crow + 512) = e1;
    }
}

// ---------------------------------------------------------------------------
// z_t[b,t,k] = sum_a tanh(cv[b,k,a] + cg[b,t,a]) * wh[a]
// Block: one b, 8 consecutive t's, half the k-range. 8 warps, warp-per-k.
// Each cv element loaded once per 8 tanh's (t-reuse in registers).
// ---------------------------------------------------------------------------
__global__ __launch_bounds__(256)
void z_kernel(const float* __restrict__ wh) {
    __shared__ float cgs[8][512];
    __shared__ float whs[512];

    const int tid = threadIdx.x;
    const int b   = blockIdx.y >> 2;
    const int t0  = (blockIdx.y & 3) * 8;
    const int klo = blockIdx.x * 98;
    const int khi = klo + 98;

    const float* cgbase = g_cg + (b * DT + t0) * DA;
    for (int i = tid; i < 8 * 512; i += 256) ((float*)cgs)[i] = cgbase[i];
    for (int i = tid; i < 512; i += 256) whs[i] = wh[i];
    __syncthreads();

    const int w = tid >> 5, lane = tid & 31;

    for (int k = klo + w; k < khi; k += 8) {
        const float* cvp = g_cv + (b * DK + k) * DA + lane;
        float zs[8];
#pragma unroll
        for (int tt = 0; tt < 8; tt++) zs[tt] = 0.f;

#pragma unroll
        for (int j = 0; j < 16; j++) {
            float v  = cvp[j * 32];
            float wv = whs[lane + j * 32];
#pragma unroll
            for (int tt = 0; tt < 8; tt++) {
                float x = v + cgs[tt][lane + j * 32];
                zs[tt] = fmaf(tanh_approx(x), wv, zs[tt]);
            }
        }
#pragma unroll
        for (int tt = 0; tt < 8; tt++) {
            float s = zs[tt];
            s += __shfl_xor_sync(0xffffffffu, s, 16);
            s += __shfl_xor_sync(0xffffffffu, s, 8);
            s += __shfl_xor_sync(0xffffffffu, s, 4);
            s += __shfl_xor_sync(0xffffffffu, s, 2);
            s += __shfl_xor_sync(0xffffffffu, s, 1);
            zs[tt] = s;
        }
        if (lane == 0) {
#pragma unroll
            for (int tt = 0; tt < 8; tt++)
                g_zt[(b * DT + t0 + tt) * DK + k] = zs[tt];
        }
    }
}

// ---------------------------------------------------------------------------
// Per row (b,t): z_ext from (cs+cg), softmax over z_t -> alpha, extended
// softmax last element -> beta. One warp per row.
// ---------------------------------------------------------------------------
__global__ __launch_bounds__(256)
void softmax_k(const float* __restrict__ wh, float* __restrict__ out) {
    const int w = threadIdx.x >> 5, lane = threadIdx.x & 31;
    const int row = blockIdx.x * 8 + w;          // 0..1023
    float* out_alpha = out + OUT_ALPHA_OFF;
    float* out_beta  = out + OUT_BETA_OFF;

    // z_ext = sum_a tanh(cs + cg) * wh
    const float* cs = g_cs + row * DA;
    const float* cg = g_cg + row * DA;
    float ze = 0.f;
#pragma unroll
    for (int j = 0; j < 16; j++) {
        int a = lane + j * 32;
        ze = fmaf(tanh_approx(cs[a] + cg[a]), wh[a], ze);
    }
    ze += __shfl_xor_sync(0xffffffffu, ze, 16);
    ze += __shfl_xor_sync(0xffffffffu, ze, 8);
    ze += __shfl_xor_sync(0xffffffffu, ze, 4);
    ze += __shfl_xor_sync(0xffffffffu, ze, 2);
    ze += __shfl_xor_sync(0xffffffffu, ze, 1);

    // softmax over 196 logits
    const float* zr = g_zt + row * DK;
    float zv[7];
    float m = -1e30f;
#pragma unroll
    for (int j = 0; j < 7; j++) {
        int k = lane + j * 32;
        zv[j] = (k < DK) ? zr[k] : -1e30f;
        m = fmaxf(m, zv[j]);
    }
    m = fmaxf(m, __shfl_xor_sync(0xffffffffu, m, 16));
    m = fmaxf(m, __shfl_xor_sync(0xffffffffu, m, 8));
    m = fmaxf(m, __shfl_xor_sync(0xffffffffu, m, 4));
    m = fmaxf(m, __shfl_xor_sync(0xffffffffu, m, 2));
    m = fmaxf(m, __shfl_xor_sync(0xffffffffu, m, 1));

    float p[7];
    float S = 0.f;
#pragma unroll
    for (int j = 0; j < 7; j++) {
        p[j] = __expf(zv[j] - m);   // padded lanes: exp(-huge) -> 0
        S += p[j];
    }
    S += __shfl_xor_sync(0xffffffffu, S, 16);
    S += __shfl_xor_sync(0xffffffffu, S, 8);
    S += __shfl_xor_sync(0xffffffffu, S, 4);
    S += __shfl_xor_sync(0xffffffffu, S, 2);
    S += __shfl_xor_sync(0xffffffffu, S, 1);

    float invS = 1.0f / S;
#pragma unroll
    for (int j = 0; j < 7; j++) {
        int k = lane + j * 32;
        if (k < DK) out_alpha[row * DK + k] = p[j] * invS;
    }

    // beta = last element of softmax over [z_t, z_ext]
    float m2  = fmaxf(m, ze);
    float eb  = __expf(ze - m2);
    float den = S * __expf(m - m2) + eb;
    if (lane == 0) out_beta[row] = eb / den;
}

// ---------------------------------------------------------------------------
// c_t[b,t,h] = sum_k alpha[b,t,k] * att[b,k,h];
// c_hat = c_t + beta * (sentinel - c_t)      -> out[0 .. B*T*H)
// Block: (b, 128-wide h chunk); 256 threads = 128 h-lanes x 2 t-groups of 16.
// ---------------------------------------------------------------------------
__global__ __launch_bounds__(256)
void ct_k(const float* __restrict__ att, const float* __restrict__ sent,
          float* __restrict__ out) {
    __shared__ float al[32][200];   // [t][k], padded row
    __shared__ float bs[32];

    const int tid = threadIdx.x;
    const int b   = blockIdx.y;
    const int hc  = blockIdx.x;
    const float* out_alpha = out + OUT_ALPHA_OFF;
    const float* out_beta  = out + OUT_BETA_OFF;

    for (int idx = tid; idx < 32 * DK; idx += 256) {
        int t = idx / DK, k = idx - t * DK;
        al[t][k] = out_alpha[(b * DT + t) * DK + k];
    }
    if (tid < 32) bs[tid] = out_beta[b * DT + tid];
    __syncthreads();

    const int tx = tid & 127, tz = tid >> 7;
    const int h  = hc * 128 + tx;

    float acc[16];
#pragma unroll
    for (int i = 0; i < 16; i++) acc[i] = 0.f;

    const float* ap = att + (b * DK) * DH + h;
#pragma unroll 4
    for (int k = 0; k < DK; k++) {
        float af = ap[k * DH];
#pragma unroll
        for (int i = 0; i < 16; i++)
            acc[i] = fmaf(al[tz * 16 + i][k], af, acc[i]);
    }

#pragma unroll
    for (int i = 0; i < 16; i++) {
        int t = tz * 16 + i;
        float bt = bs[t];
        int off = (b * DT + t) * DH + h;
        out[off] = fmaf(bt, sent[off] - acc[i], acc[i]);
    }
}

// ---------------------------------------------------------------------------
extern "C" void kernel_launch(void* const* d_in, const int* in_sizes, int n_in,
                              void* d_out, int out_size) {
    const float* att = (const float*)d_in[0];
    const float* hid = (const float*)d_in[1];
    const float* sen = (const float*)d_in[2];
    const float* Wv  = (const float*)d_in[3];
    const float* Wg  = (const float*)d_in[4];
    const float* Ws  = (const float*)d_in[5];
    const float* wh  = (const float*)d_in[6];
    float* out = (float*)d_out;

    gemm_k<0><<<dim3(8, 49), 256>>>(att, Wv);   // cv : 6272 x 512
    gemm_k<1><<<dim3(8, 8),  256>>>(hid, Wg);   // cg : 1024 x 512
    gemm_k<2><<<dim3(8, 8),  256>>>(sen, Ws);   // cs : 1024 x 512
    z_kernel<<<dim3(2, 128), 256>>>(wh);
    softmax_k<<<128, 256>>>(wh, out);
    ct_k<<<dim3(4, 32), 256>>>(att, sen, out);
}

// round 2
// speedup vs baseline: 1.4386x; 1.4386x over previous
#include <cuda_runtime.h>

// Problem dims (fixed by the dataset)
#define DB 32
#define DT 32
#define DK 196
#define DH 512
#define DA 512

#define OUT_ALPHA_OFF (DB*DT*DH)            // 524288
#define OUT_BETA_OFF  (DB*DT*DH + DB*DT*DK) // 724992

// Scratch (allocation-free rule: __device__ globals)
__device__ float g_cv[DB*DK*DA];   // att_feats @ Wv   (6272 x 512)
__device__ float g_cg[DB*DT*DA];   // hiddens   @ Wg   (1024 x 512)
__device__ float g_cs[DB*DT*DA];   // sentinel  @ Ws   (1024 x 512)
__device__ float g_zt[DB*DT*DK];   // logits           (1024 x 196)

// ---------------------------------------------------------------------------
// helpers
// ---------------------------------------------------------------------------
__device__ __forceinline__ void fma2(unsigned long long& c,
                                     unsigned long long a,
                                     unsigned long long b) {
    asm("fma.rn.f32x2 %0, %1, %2, %0;" : "+l"(c) : "l"(a), "l"(b));
}
__device__ __forceinline__ unsigned long long dup2(float s) {
    unsigned long long d;
    asm("mov.b64 %0, {%1, %1};" : "=l"(d) : "r"(__float_as_uint(s)));
    return d;
}
__device__ __forceinline__ unsigned long long pack2(float a, float b) {
    unsigned long long d;
    asm("mov.b64 %0, {%1, %2};" : "=l"(d) : "f"(a), "f"(b));
    return d;
}
__device__ __forceinline__ float lo2(unsigned long long v) {
    float a; unsigned hi;
    asm("mov.b64 {%0, %1}, %2;" : "=f"(a), "=r"(hi) : "l"(v));
    return a;
}
__device__ __forceinline__ float hi2(unsigned long long v) {
    unsigned lo; float b;
    asm("mov.b64 {%0, %1}, %2;" : "=r"(lo), "=f"(b) : "l"(v));
    return b;
}
__device__ __forceinline__ float tanh_approx(float x) {
    float y;
    asm("tanh.approx.f32 %0, %1;" : "=f"(y) : "f"(x));
    return y;
}

// ---------------------------------------------------------------------------
// GEMM: C[M,512] = A[M,512] @ W[512,512] fp32.
// 128x128 block tile, BK=8, 256 threads, 8x8 per-thread via FFMA2 m-pairs,
// double-buffered smem, split-column mapping (tx*4 / 64+tx*4) for
// conflict-free LDS.128.
// ---------------------------------------------------------------------------
template<int OUTSEL>
__global__ __launch_bounds__(256, 2)
void gemm_k(const float* __restrict__ Am, const float* __restrict__ Wm) {
    float* Cm = (OUTSEL == 0) ? g_cv : ((OUTSEL == 1) ? g_cg : g_cs);

    __shared__ __align__(16) float As[2][8][128];  // [buf][k][m]
    __shared__ __align__(16) float Bs[2][8][128];  // [buf][k][n]

    const int tid = threadIdx.x;
    const int tx  = tid & 15;
    const int ty  = tid >> 4;
    const int m0  = blockIdx.y * 128;
    const int n0  = blockIdx.x * 128;

    // A loader: 128 rows x 8 k; thread -> (row = tid%128, kcol4 = (tid/128)*4)
    const int arow = tid & 127;
    const int acol = (tid >> 7) * 4;
    // B loader: 8 k x 128 n; thread -> (k = tid>>5, col4 = (tid&31)*4)
    const int brow = tid >> 5;
    const int bcol = (tid & 31) * 4;

    const float* Ap = Am + (m0 + arow) * 512 + acol;
    const float* Bp = Wm + brow * 512 + n0 + bcol;

    unsigned long long acc[4][8];
#pragma unroll
    for (int i = 0; i < 4; i++)
#pragma unroll
        for (int j = 0; j < 8; j++) acc[i][j] = 0ull;

    float4 av = *(const float4*)(Ap);
    float4 bv = *(const float4*)(Bp);

    // store first tile
    As[0][acol + 0][arow] = av.x;
    As[0][acol + 1][arow] = av.y;
    As[0][acol + 2][arow] = av.z;
    As[0][acol + 3][arow] = av.w;
    *(float4*)&Bs[0][brow][bcol] = bv;
    __syncthreads();

    int buf = 0;
    for (int k0 = 0; k0 < 512; k0 += 8) {
        const bool more = (k0 + 8 < 512);
        if (more) {
            av = *(const float4*)(Ap + k0 + 8);
            bv = *(const float4*)(Bp + (k0 + 8) * 512);
        }
#pragma unroll
        for (int kk = 0; kk < 8; kk++) {
            ulonglong2 a01 = *(const ulonglong2*)&As[buf][kk][ty * 4];
            ulonglong2 a23 = *(const ulonglong2*)&As[buf][kk][64 + ty * 4];
            float4 b0 = *(const float4*)&Bs[buf][kk][tx * 4];
            float4 b1 = *(const float4*)&Bs[buf][kk][64 + tx * 4];
            unsigned long long bd0 = dup2(b0.x), bd1 = dup2(b0.y);
            unsigned long long bd2 = dup2(b0.z), bd3 = dup2(b0.w);
            unsigned long long bd4 = dup2(b1.x), bd5 = dup2(b1.y);
            unsigned long long bd6 = dup2(b1.z), bd7 = dup2(b1.w);
            fma2(acc[0][0], a01.x, bd0); fma2(acc[0][1], a01.x, bd1);
            fma2(acc[0][2], a01.x, bd2); fma2(acc[0][3], a01.x, bd3);
            fma2(acc[0][4], a01.x, bd4); fma2(acc[0][5], a01.x, bd5);
            fma2(acc[0][6], a01.x, bd6); fma2(acc[0][7], a01.x, bd7);
            fma2(acc[1][0], a01.y, bd0); fma2(acc[1][1], a01.y, bd1);
            fma2(acc[1][2], a01.y, bd2); fma2(acc[1][3], a01.y, bd3);
            fma2(acc[1][4], a01.y, bd4); fma2(acc[1][5], a01.y, bd5);
            fma2(acc[1][6], a01.y, bd6); fma2(acc[1][7], a01.y, bd7);
            fma2(acc[2][0], a23.x, bd0); fma2(acc[2][1], a23.x, bd1);
            fma2(acc[2][2], a23.x, bd2); fma2(acc[2][3], a23.x, bd3);
            fma2(acc[2][4], a23.x, bd4); fma2(acc[2][5], a23.x, bd5);
            fma2(acc[2][6], a23.x, bd6); fma2(acc[2][7], a23.x, bd7);
            fma2(acc[3][0], a23.y, bd0); fma2(acc[3][1], a23.y, bd1);
            fma2(acc[3][2], a23.y, bd2); fma2(acc[3][3], a23.y, bd3);
            fma2(acc[3][4], a23.y, bd4); fma2(acc[3][5], a23.y, bd5);
            fma2(acc[3][6], a23.y, bd6); fma2(acc[3][7], a23.y, bd7);
        }
        if (more) {
            As[buf ^ 1][acol + 0][arow] = av.x;
            As[buf ^ 1][acol + 1][arow] = av.y;
            As[buf ^ 1][acol + 2][arow] = av.z;
            As[buf ^ 1][acol + 3][arow] = av.w;
            *(float4*)&Bs[buf ^ 1][brow][bcol] = bv;
            __syncthreads();
        }
        buf ^= 1;
    }

    // epilogue: 4 m-pairs x 8 n (cols tx*4..+3 and 64+tx*4..+3)
#pragma unroll
    for (int mp = 0; mp < 4; mp++) {
        const int rbase = (mp < 2) ? (ty * 4 + 2 * mp) : (64 + ty * 4 + 2 * (mp - 2));
        float* c0 = Cm + (m0 + rbase) * 512 + n0;
        float* c1 = c0 + 512;
        float4 e;
        e = make_float4(lo2(acc[mp][0]), lo2(acc[mp][1]), lo2(acc[mp][2]), lo2(acc[mp][3]));
        *(float4*)(c0 + tx * 4) = e;
        e = make_float4(lo2(acc[mp][4]), lo2(acc[mp][5]), lo2(acc[mp][6]), lo2(acc[mp][7]));
        *(float4*)(c0 + 64 + tx * 4) = e;
        e = make_float4(hi2(acc[mp][0]), hi2(acc[mp][1]), hi2(acc[mp][2]), hi2(acc[mp][3]));
        *(float4*)(c1 + tx * 4) = e;
        e = make_float4(hi2(acc[mp][4]), hi2(acc[mp][5]), hi2(acc[mp][6]), hi2(acc[mp][7]));
        *(float4*)(c1 + 64 + tx * 4) = e;
    }
}

// ---------------------------------------------------------------------------
// z_t[b,t,k] = sum_a tanh(cv[b,k,a] + cg[b,t,a]) * wh[a]
// Block: one b, 8 t's, half the k-range; warp handles k-PAIRS (KU=2) so each
// cg LDS.64 feeds 4 elements. Accumulate with FMA2 on packed tanh pairs.
// ---------------------------------------------------------------------------
__global__ __launch_bounds__(256, 2)
void z_kernel(const float* __restrict__ wh) {
    __shared__ __align__(16) float cgs[8][512];
    __shared__ __align__(16) float whs[512];

    const int tid = threadIdx.x;
    const int b   = blockIdx.y >> 2;
    const int t0  = (blockIdx.y & 3) * 8;
    const int klo = blockIdx.x * 98;          // 98 k's per block (even)

    const float* cgbase = g_cg + (b * DT + t0) * DA;
    for (int i = tid; i < 8 * 512; i += 256) ((float*)cgs)[i] = cgbase[i];
    for (int i = tid; i < 512; i += 256) whs[i] = wh[i];
    __syncthreads();

    const int w = tid >> 5, lane = tid & 31;

    for (int p = w; p < 49; p += 8) {         // 49 k-pairs per block
        const int k0 = klo + 2 * p;
        const float2* cv0 = (const float2*)(g_cv + (b * DK + k0) * DA);
        const float2* cv1 = cv0 + 256;        // next k row

        unsigned long long acc0[8], acc1[8];
#pragma unroll
        for (int tt = 0; tt < 8; tt++) { acc0[tt] = 0ull; acc1[tt] = 0ull; }

#pragma unroll 2
        for (int j = 0; j < 8; j++) {
            const int ai = lane + j * 32;     // float2 index (covers 2 a's)
            float2 v0 = cv0[ai];
            float2 v1 = cv1[ai];
            unsigned long long whd = *((const unsigned long long*)whs + ai);
#pragma unroll
            for (int tt = 0; tt < 8; tt++) {
                float2 c = *((const float2*)cgs[tt] + ai);
                unsigned long long t0p =
                    pack2(tanh_approx(v0.x + c.x), tanh_approx(v0.y + c.y));
                fma2(acc0[tt], t0p, whd);
                unsigned long long t1p =
                    pack2(tanh_approx(v1.x + c.x), tanh_approx(v1.y + c.y));
                fma2(acc1[tt], t1p, whd);
            }
        }

#pragma unroll
        for (int tt = 0; tt < 8; tt++) {
            float s0 = lo2(acc0[tt]) + hi2(acc0[tt]);
            float s1 = lo2(acc1[tt]) + hi2(acc1[tt]);
            s0 += __shfl_xor_sync(0xffffffffu, s0, 16);
            s1 += __shfl_xor_sync(0xffffffffu, s1, 16);
            s0 += __shfl_xor_sync(0xffffffffu, s0, 8);
            s1 += __shfl_xor_sync(0xffffffffu, s1, 8);
            s0 += __shfl_xor_sync(0xffffffffu, s0, 4);
            s1 += __shfl_xor_sync(0xffffffffu, s1, 4);
            s0 += __shfl_xor_sync(0xffffffffu, s0, 2);
            s1 += __shfl_xor_sync(0xffffffffu, s1, 2);
            s0 += __shfl_xor_sync(0xffffffffu, s0, 1);
            s1 += __shfl_xor_sync(0xffffffffu, s1, 1);
            if (lane == 0) {
                float* zr = g_zt + (b * DT + t0 + tt) * DK;
                zr[k0]     = s0;
                zr[k0 + 1] = s1;
            }
        }
    }
}

// ---------------------------------------------------------------------------
// Per row (b,t): z_ext from (cs+cg), softmax over z_t -> alpha, extended
// softmax last element -> beta. One warp per row.
// ---------------------------------------------------------------------------
__global__ __launch_bounds__(256)
void softmax_k(const float* __restrict__ wh, float* __restrict__ out) {
    const int w = threadIdx.x >> 5, lane = threadIdx.x & 31;
    const int row = blockIdx.x * 8 + w;          // 0..1023
    float* out_alpha = out + OUT_ALPHA_OFF;
    float* out_beta  = out + OUT_BETA_OFF;

    const float* cs = g_cs + row * DA;
    const float* cg = g_cg + row * DA;
    float ze = 0.f;
#pragma unroll
    for (int j = 0; j < 16; j++) {
        int a = lane + j * 32;
        ze = fmaf(tanh_approx(cs[a] + cg[a]), wh[a], ze);
    }
    ze += __shfl_xor_sync(0xffffffffu, ze, 16);
    ze += __shfl_xor_sync(0xffffffffu, ze, 8);
    ze += __shfl_xor_sync(0xffffffffu, ze, 4);
    ze += __shfl_xor_sync(0xffffffffu, ze, 2);
    ze += __shfl_xor_sync(0xffffffffu, ze, 1);

    const float* zr = g_zt + row * DK;
    float zv[7];
    float m = -1e30f;
#pragma unroll
    for (int j = 0; j < 7; j++) {
        int k = lane + j * 32;
        zv[j] = (k < DK) ? zr[k] : -1e30f;
        m = fmaxf(m, zv[j]);
    }
    m = fmaxf(m, __shfl_xor_sync(0xffffffffu, m, 16));
    m = fmaxf(m, __shfl_xor_sync(0xffffffffu, m, 8));
    m = fmaxf(m, __shfl_xor_sync(0xffffffffu, m, 4));
    m = fmaxf(m, __shfl_xor_sync(0xffffffffu, m, 2));
    m = fmaxf(m, __shfl_xor_sync(0xffffffffu, m, 1));

    float p[7];
    float S = 0.f;
#pragma unroll
    for (int j = 0; j < 7; j++) {
        p[j] = __expf(zv[j] - m);
        S += p[j];
    }
    S += __shfl_xor_sync(0xffffffffu, S, 16);
    S += __shfl_xor_sync(0xffffffffu, S, 8);
    S += __shfl_xor_sync(0xffffffffu, S, 4);
    S += __shfl_xor_sync(0xffffffffu, S, 2);
    S += __shfl_xor_sync(0xffffffffu, S, 1);

    float invS = 1.0f / S;
#pragma unroll
    for (int j = 0; j < 7; j++) {
        int k = lane + j * 32;
        if (k < DK) out_alpha[row * DK + k] = p[j] * invS;
    }

    float m2  = fmaxf(m, ze);
    float eb  = __expf(ze - m2);
    float den = S * __expf(m - m2) + eb;
    if (lane == 0) out_beta[row] = eb / den;
}

// ---------------------------------------------------------------------------
// c_t[b,t,h] = sum_k alpha[b,t,k] * att[b,k,h];  c_hat = c_t + beta*(sent-c_t)
// Block: (4 t's, one b). 128 threads; warp covers 128 h via float4;
// alpha smem-broadcast.
// ---------------------------------------------------------------------------
__global__ __launch_bounds__(128)
void ct_k(const float* __restrict__ att, const float* __restrict__ sent,
          float* __restrict__ out) {
    __shared__ float al[4][DK];
    __shared__ float bsm[4];

    const int tid = threadIdx.x;
    const int b   = blockIdx.y;
    const int t0  = blockIdx.x * 4;
    const float* out_alpha = out + OUT_ALPHA_OFF;
    const float* out_beta  = out + OUT_BETA_OFF;

    for (int i = tid; i < 4 * DK; i += 128) {
        int t = i / DK, k = i - t * DK;
        al[t][k] = out_alpha[(b * DT + t0 + t) * DK + k];
    }
    if (tid < 4) bsm[tid] = out_beta[b * DT + t0 + tid];
    __syncthreads();

    const int w = tid >> 5, lane = tid & 31;
    const int h = w * 128 + lane * 4;

    float4 acc[4];
#pragma unroll
    for (int i = 0; i < 4; i++) acc[i] = make_float4(0.f, 0.f, 0.f, 0.f);

    const float* ap = att + (b * DK) * DH + h;
#pragma unroll 4
    for (int k = 0; k < DK; k++) {
        float4 af = *(const float4*)(ap + k * DH);
#pragma unroll
        for (int tt = 0; tt < 4; tt++) {
            float a = al[tt][k];
            acc[tt].x = fmaf(a, af.x, acc[tt].x);
            acc[tt].y = fmaf(a, af.y, acc[tt].y);
            acc[tt].z = fmaf(a, af.z, acc[tt].z);
            acc[tt].w = fmaf(a, af.w, acc[tt].w);
        }
    }

#pragma unroll
    for (int tt = 0; tt < 4; tt++) {
        const int off = (b * DT + t0 + tt) * DH + h;
        float4 s = *(const float4*)(sent + off);
        float bt = bsm[tt];
        float4 r;
        r.x = fmaf(bt, s.x - acc[tt].x, acc[tt].x);
        r.y = fmaf(bt, s.y - acc[tt].y, acc[tt].y);
        r.z = fmaf(bt, s.z - acc[tt].z, acc[tt].z);
        r.w = fmaf(bt, s.w - acc[tt].w, acc[tt].w);
        *(float4*)(out + off) = r;
    }
}

// ---------------------------------------------------------------------------
extern "C" void kernel_launch(void* const* d_in, const int* in_sizes, int n_in,
                              void* d_out, int out_size) {
    const float* att = (const float*)d_in[0];
    const float* hid = (const float*)d_in[1];
    const float* sen = (const float*)d_in[2];
    const float* Wv  = (const float*)d_in[3];
    const float* Wg  = (const float*)d_in[4];
    const float* Ws  = (const float*)d_in[5];
    const float* wh  = (const float*)d_in[6];
    float* out = (float*)d_out;

    gemm_k<0><<<dim3(4, 49), 256>>>(att, Wv);   // cv : 6272 x 512
    gemm_k<1><<<dim3(4, 8),  256>>>(hid, Wg);   // cg : 1024 x 512
    gemm_k<2><<<dim3(4, 8),  256>>>(sen, Ws);   // cs : 1024 x 512
    z_kernel<<<dim3(2, 128), 256>>>(wh);
    softmax_k<<<128, 256>>>(wh, out);
    ct_k<<<dim3(8, 32), 128>>>(att, sen, out);
}

// round 5
// speedup vs baseline: 1.9336x; 1.3440x over previous
#include <cuda_runtime.h>
#include <cuda_bf16.h>
#include <cstdint>

// Problem dims (fixed by the dataset)
#define DB 32
#define DT 32
#define DK 196
#define DH 512
#define DA 512

#define OUT_ALPHA_OFF (DB*DT*DH)            // 524288
#define OUT_BETA_OFF  (DB*DT*DH + DB*DT*DK) // 724992

// Scratch (allocation-free rule: __device__ globals)
__device__ float g_cv[DB*DK*DA];   // att_feats @ Wv   (6272 x 512)
__device__ float g_cg[DB*DT*DA];   // hiddens   @ Wg   (1024 x 512)
__device__ float g_cs[DB*DT*DA];   // sentinel  @ Ws   (1024 x 512)
__device__ float g_zt[DB*DT*DK];   // logits           (1024 x 196)
__device__ __nv_bfloat16 g_wt_hi[3*512*512];  // W^T hi, [wsel][n][k]
__device__ __nv_bfloat16 g_wt_lo[3*512*512];  // W^T lo

// ---------------------------------------------------------------------------
// helpers
// ---------------------------------------------------------------------------
__device__ __forceinline__ uint32_t smem_to_u32(const void* p) {
    uint32_t a;
    asm("{ .reg .u64 t; cvta.to.shared.u64 t, %1; cvt.u32.u64 %0, t; }"
        : "=r"(a) : "l"(p));
    return a;
}
#define SWZ(o) ((o) ^ (((o) >> 3) & 0x70))

__device__ __forceinline__ void ldsm_x4(uint32_t* r, uint32_t addr) {
    asm volatile("ldmatrix.sync.aligned.m8n8.x4.shared.b16 {%0,%1,%2,%3}, [%4];"
        : "=r"(r[0]), "=r"(r[1]), "=r"(r[2]), "=r"(r[3]) : "r"(addr));
}
__device__ __forceinline__ void mma16816(float* c, const uint32_t* a,
                                         const uint32_t* b) {
    asm volatile(
        "mma.sync.aligned.m16n8k16.row.col.f32.bf16.bf16.f32 "
        "{%0,%1,%2,%3}, {%4,%5,%6,%7}, {%8,%9}, {%0,%1,%2,%3};"
        : "+f"(c[0]), "+f"(c[1]), "+f"(c[2]), "+f"(c[3])
        : "r"(a[0]), "r"(a[1]), "r"(a[2]), "r"(a[3]), "r"(b[0]), "r"(b[1]));
}
__device__ __forceinline__ void fma2(unsigned long long& c,
                                     unsigned long long a,
                                     unsigned long long b) {
    asm("fma.rn.f32x2 %0, %1, %2, %0;" : "+l"(c) : "l"(a), "l"(b));
}
__device__ __forceinline__ unsigned long long pack2(float a, float b) {
    unsigned long long d;
    asm("mov.b64 %0, {%1, %2};" : "=l"(d) : "f"(a), "f"(b));
    return d;
}
__device__ __forceinline__ float lo2(unsigned long long v) {
    float a; unsigned hi;
    asm("mov.b64 {%0, %1}, %2;" : "=f"(a), "=r"(hi) : "l"(v));
    return a;
}
__device__ __forceinline__ float hi2(unsigned long long v) {
    unsigned lo; float b;
    asm("mov.b64 {%0, %1}, %2;" : "=r"(lo), "=f"(b) : "l"(v));
    return b;
}
__device__ __forceinline__ float tanh_approx(float x) {
    float y;
    asm("tanh.approx.f32 %0, %1;" : "=f"(y) : "f"(x));
    return y;
}

// ---------------------------------------------------------------------------
// W transpose + bf16 hi/lo split:  g_wt_{hi,lo}[wsel][n][k] = split(W[k][n])
// ---------------------------------------------------------------------------
__global__ void conv_w(const float* __restrict__ Wv,
                       const float* __restrict__ Wg,
                       const float* __restrict__ Ws) {
    __shared__ float tile[32][33];
    const int wsel = blockIdx.z;
    const float* W = (wsel == 0) ? Wv : ((wsel == 1) ? Wg : Ws);
    const int kb = blockIdx.y * 32, nb = blockIdx.x * 32;
    const int tx = threadIdx.x, ty = threadIdx.y;   // 32 x 8

#pragma unroll
    for (int i = 0; i < 32; i += 8)
        tile[ty + i][tx] = W[(kb + ty + i) * 512 + nb + tx];
    __syncthreads();

    __nv_bfloat16* oh = g_wt_hi + wsel * 262144;
    __nv_bfloat16* ol = g_wt_lo + wsel * 262144;
#pragma unroll
    for (int i = 0; i < 32; i += 8) {
        float v = tile[tx][ty + i];
        __nv_bfloat16 h = __float2bfloat16(v);
        oh[(nb + ty + i) * 512 + kb + tx] = h;
        ol[(nb + ty + i) * 512 + kb + tx] = __float2bfloat16(v - __bfloat162float(h));
    }
}

// ---------------------------------------------------------------------------
// Fused HMMA GEMM: all 260 (128x128) C-tiles of cv|cg|cs in one grid.
// Split-bf16: C = Ahi*Bhi + Ahi*Blo + Alo*Bhi  (fp32 accum in registers).
// mma.sync m16n8k16, ldmatrix from SW128-swizzled smem, K-chunk 64,
// double-buffered smem + reg prefetch.
// smem layout per buffer: ASH(16K) ASL(16K) BSH(16K) BSL(16K) = 64KB; x2.
// ---------------------------------------------------------------------------
#define TILE_B  16384
#define BUF_B   65536

__global__ __launch_bounds__(256, 1)
void gemm_mma(const float* __restrict__ att,
              const float* __restrict__ hid,
              const float* __restrict__ sen) {
    extern __shared__ __align__(1024) char smem[];
    const uint32_t sbase = smem_to_u32(smem);

    const int tid  = threadIdx.x;
    const int wid  = tid >> 5, lane = tid & 31;
    const int wm   = (wid & 1) * 64;    // warp m offset in tile
    const int wn   = (wid >> 1) * 32;   // warp n offset in tile

    // job decode: 260 = 196(cv) + 32(cg) + 32(cs)
    const int bid = blockIdx.x;
    const float* Ag; float* Cg; int wsel, mt, nt;
    if (bid < 196)      { mt = bid >> 2; nt = bid & 3; Ag = att; Cg = g_cv; wsel = 0; }
    else if (bid < 228) { int i = bid - 196; mt = i >> 2; nt = i & 3; Ag = hid; Cg = g_cg; wsel = 1; }
    else                { int i = bid - 228; mt = i >> 2; nt = i & 3; Ag = sen; Cg = g_cs; wsel = 2; }
    const int m0 = mt * 128, n0 = nt * 128;

    const __nv_bfloat16* WtH = g_wt_hi + wsel * 262144;
    const __nv_bfloat16* WtL = g_wt_lo + wsel * 262144;

    // loader mappings
    const int a_row = tid >> 1;                 // pattern base (see loop)
    (void)a_row;

    float c[16][4];
#pragma unroll
    for (int i = 0; i < 16; i++)
#pragma unroll
        for (int j = 0; j < 4; j++) c[i][j] = 0.f;

    // prefetch registers for one chunk
    float4 pA[8];
    uint4  pBh[4], pBl[4];

    // --- load chunk 0 to regs ---
#pragma unroll
    for (int i = 0; i < 8; i++) {
        int idx = tid + i * 256;            // 0..2047
        int row = idx >> 4, c4 = idx & 15;  // 128 rows x 16 float4-cols
        pA[i] = *(const float4*)(Ag + (m0 + row) * 512 + c4 * 4);
    }
#pragma unroll
    for (int i = 0; i < 4; i++) {
        int idx = tid + i * 256;            // 0..1023
        int row = idx >> 3, ch = idx & 7;   // 128 n-rows x 8 uint4-chunks
        pBh[i] = *(const uint4*)(WtH + (n0 + row) * 512 + ch * 8);
        pBl[i] = *(const uint4*)(WtL + (n0 + row) * 512 + ch * 8);
    }

    for (int cch = 0; cch < 8; cch++) {
        const uint32_t buf = sbase + (cch & 1) * BUF_B;
        const uint32_t ASH = buf, ASL = buf + TILE_B;
        const uint32_t BSH = buf + 2 * TILE_B, BSL = buf + 3 * TILE_B;

        // store prefetched chunk into smem (hi/lo split for A)
#pragma unroll
        for (int i = 0; i < 8; i++) {
            int idx = tid + i * 256;
            int row = idx >> 4, c4 = idx & 15;
            float4 v = pA[i];
            __nv_bfloat162 h0, h1, l0, l1;
            h0.x = __float2bfloat16(v.x); h0.y = __float2bfloat16(v.y);
            h1.x = __float2bfloat16(v.z); h1.y = __float2bfloat16(v.w);
            l0.x = __float2bfloat16(v.x - __bfloat162float(h0.x));
            l0.y = __float2bfloat16(v.y - __bfloat162float(h0.y));
            l1.x = __float2bfloat16(v.z - __bfloat162float(h1.x));
            l1.y = __float2bfloat16(v.w - __bfloat162float(h1.y));
            uint32_t off = SWZ((uint32_t)(row * 128 + c4 * 8));
            *(__nv_bfloat162*)(smem + (ASH - sbase) + off)     = h0;
            *(__nv_bfloat162*)(smem + (ASH - sbase) + off + 4) = h1;
            *(__nv_bfloat162*)(smem + (ASL - sbase) + off)     = l0;
            *(__nv_bfloat162*)(smem + (ASL - sbase) + off + 4) = l1;
        }
#pragma unroll
        for (int i = 0; i < 4; i++) {
            int idx = tid + i * 256;
            int row = idx >> 3, ch = idx & 7;
            uint32_t off = SWZ((uint32_t)(row * 128 + ch * 16));
            *(uint4*)(smem + (BSH - sbase) + off) = pBh[i];
            *(uint4*)(smem + (BSL - sbase) + off) = pBl[i];
        }
        __syncthreads();

        // prefetch next chunk
        if (cch < 7) {
            const int k0 = (cch + 1) * 64;
#pragma unroll
            for (int i = 0; i < 8; i++) {
                int idx = tid + i * 256;
                int row = idx >> 4, c4 = idx & 15;
                pA[i] = *(const float4*)(Ag + (m0 + row) * 512 + k0 + c4 * 4);
            }
#pragma unroll
            for (int i = 0; i < 4; i++) {
                int idx = tid + i * 256;
                int row = idx >> 3, ch = idx & 7;
                pBh[i] = *(const uint4*)(WtH + (n0 + row) * 512 + k0 + ch * 8);
                pBl[i] = *(const uint4*)(WtL + (n0 + row) * 512 + k0 + ch * 8);
            }
        }

        // MMA over 4 k-steps of 16
#pragma unroll
        for (int ks = 0; ks < 4; ks++) {
            const uint32_t kbA = (uint32_t)((ks * 16 + (lane >> 4) * 8) * 2);
            uint32_t ah[4][4], al[4][4];
#pragma unroll
            for (int mtile = 0; mtile < 4; mtile++) {
                uint32_t rowb = (uint32_t)((wm + mtile * 16 + (lane & 15)) * 128);
                uint32_t off  = SWZ(rowb + kbA);
                ldsm_x4(ah[mtile], ASH + off);
                ldsm_x4(al[mtile], ASL + off);
            }
            const uint32_t kbB = (uint32_t)((ks * 16 + ((lane >> 3) & 1) * 8) * 2);
            uint32_t bh[2][4], bl[2][4];
#pragma unroll
            for (int p = 0; p < 2; p++) {
                uint32_t nrow = (uint32_t)(wn + p * 16 + (lane & 7) +
                                           ((lane >> 4) & 1) * 8);
                uint32_t off = SWZ(nrow * 128 + kbB);
                ldsm_x4(bh[p], BSH + off);
                ldsm_x4(bl[p], BSL + off);
            }
#pragma unroll
            for (int mtile = 0; mtile < 4; mtile++) {
#pragma unroll
                for (int p = 0; p < 2; p++) {
#pragma unroll
                    for (int h = 0; h < 2; h++) {
                        float* cc = c[mtile * 4 + p * 2 + h];
                        mma16816(cc, ah[mtile], &bh[p][2 * h]);
                        mma16816(cc, ah[mtile], &bl[p][2 * h]);
                        mma16816(cc, al[mtile], &bh[p][2 * h]);
                    }
                }
            }
        }
        __syncthreads();
    }

    // epilogue: c[mtile*4 + ntile] -> C[m0+wm+mtile*16 + r][n0+wn+ntile*8 + col]
    const int r0 = lane >> 2, col = (lane & 3) * 2;
#pragma unroll
    for (int mtile = 0; mtile < 4; mtile++) {
#pragma unroll
        for (int ntile = 0; ntile < 4; ntile++) {
            float* cc = c[mtile * 4 + ntile];
            float* base = Cg + (m0 + wm + mtile * 16 + r0) * 512
                             + n0 + wn + ntile * 8 + col;
            *(float2*)(base)            = make_float2(cc[0], cc[1]);
            *(float2*)(base + 8 * 512)  = make_float2(cc[2], cc[3]);
        }
    }
}

// ---------------------------------------------------------------------------
// z_t[b,t,k] = sum_a tanh(cv[b,k,a] + cg[b,t,a]) * wh[a]
// Block: one b, 8 t's, half k-range; warp per k; float4 a-vectors; FMA2 accum.
// ---------------------------------------------------------------------------
__global__ __launch_bounds__(256, 3)
void z_kernel(const float* __restrict__ wh) {
    __shared__ __align__(16) float cgs[8][512];
    __shared__ __align__(16) float whs[512];

    const int tid = threadIdx.x;
    const int b   = blockIdx.y >> 2;
    const int t0  = (blockIdx.y & 3) * 8;
    const int klo = blockIdx.x * 98;
    const int khi = klo + 98;

    const float* cgbase = g_cg + (b * DT + t0) * DA;
    for (int i = tid; i < 8 * 512; i += 256) ((float*)cgs)[i] = cgbase[i];
    for (int i = tid; i < 512; i += 256) whs[i] = wh[i];
    __syncthreads();

    const int w = tid >> 5, lane = tid & 31;

    for (int k = klo + w; k < khi; k += 8) {
        const float4* cvp = (const float4*)(g_cv + (b * DK + k) * DA);

        unsigned long long acc[8];
#pragma unroll
        for (int tt = 0; tt < 8; tt++) acc[tt] = 0ull;

#pragma unroll
        for (int j = 0; j < 4; j++) {
            const int i = lane + j * 32;          // float4 index: a = 4*i..4*i+3
            float4 v = cvp[i];
            ulonglong2 whv = ((const ulonglong2*)whs)[i];
#pragma unroll
            for (int tt = 0; tt < 8; tt++) {
                float4 cvec = ((const float4*)cgs[tt])[i];
                unsigned long long p0 = pack2(tanh_approx(v.x + cvec.x),
                                              tanh_approx(v.y + cvec.y));
                fma2(acc[tt], p0, whv.x);
                unsigned long long p1 = pack2(tanh_approx(v.z + cvec.z),
                                              tanh_approx(v.w + cvec.w));
                fma2(acc[tt], p1, whv.y);
            }
        }

#pragma unroll
        for (int tt = 0; tt < 8; tt++) {
            float s = lo2(acc[tt]) + hi2(acc[tt]);
            s += __shfl_xor_sync(0xffffffffu, s, 16);
            s += __shfl_xor_sync(0xffffffffu, s, 8);
            s += __shfl_xor_sync(0xffffffffu, s, 4);
            s += __shfl_xor_sync(0xffffffffu, s, 2);
            s += __shfl_xor_sync(0xffffffffu, s, 1);
            if (lane == 0) g_zt[(b * DT + t0 + tt) * DK + k] = s;
        }
    }
}

// ---------------------------------------------------------------------------
// Per row (b,t): z_ext from (cs+cg), softmax -> alpha, extended -> beta.
// ---------------------------------------------------------------------------
__global__ __launch_bounds__(256)
void softmax_k(const float* __restrict__ wh, float* __restrict__ out) {
    const int w = threadIdx.x >> 5, lane = threadIdx.x & 31;
    const int row = blockIdx.x * 8 + w;          // 0..1023
    float* out_alpha = out + OUT_ALPHA_OFF;
    float* out_beta  = out + OUT_BETA_OFF;

    const float* cs = g_cs + row * DA;
    const float* cg = g_cg + row * DA;
    float ze = 0.f;
#pragma unroll
    for (int j = 0; j < 16; j++) {
        int a = lane + j * 32;
        ze = fmaf(tanh_approx(cs[a] + cg[a]), wh[a], ze);
    }
    ze += __shfl_xor_sync(0xffffffffu, ze, 16);
    ze += __shfl_xor_sync(0xffffffffu, ze, 8);
    ze += __shfl_xor_sync(0xffffffffu, ze, 4);
    ze += __shfl_xor_sync(0xffffffffu, ze, 2);
    ze += __shfl_xor_sync(0xffffffffu, ze, 1);

    const float* zr = g_zt + row * DK;
    float zv[7];
    float m = -1e30f;
#pragma unroll
    for (int j = 0; j < 7; j++) {
        int k = lane + j * 32;
        zv[j] = (k < DK) ? zr[k] : -1e30f;
        m = fmaxf(m, zv[j]);
    }
    m = fmaxf(m, __shfl_xor_sync(0xffffffffu, m, 16));
    m = fmaxf(m, __shfl_xor_sync(0xffffffffu, m, 8));
    m = fmaxf(m, __shfl_xor_sync(0xffffffffu, m, 4));
    m = fmaxf(m, __shfl_xor_sync(0xffffffffu, m, 2));
    m = fmaxf(m, __shfl_xor_sync(0xffffffffu, m, 1));

    float p[7];
    float S = 0.f;
#pragma unroll
    for (int j = 0; j < 7; j++) {
        p[j] = __expf(zv[j] - m);
        S += p[j];
    }
    S += __shfl_xor_sync(0xffffffffu, S, 16);
    S += __shfl_xor_sync(0xffffffffu, S, 8);
    S += __shfl_xor_sync(0xffffffffu, S, 4);
    S += __shfl_xor_sync(0xffffffffu, S, 2);
    S += __shfl_xor_sync(0xffffffffu, S, 1);

    float invS = 1.0f / S;
#pragma unroll
    for (int j = 0; j < 7; j++) {
        int k = lane + j * 32;
        if (k < DK) out_alpha[row * DK + k] = p[j] * invS;
    }

    float m2  = fmaxf(m, ze);
    float eb  = __expf(ze - m2);
    float den = S * __expf(m - m2) + eb;
    if (lane == 0) out_beta[row] = eb / den;
}

// ---------------------------------------------------------------------------
// c_t[b,t,h] = sum_k alpha[b,t,k] * att[b,k,h];  c_hat = c_t + beta*(sent-c_t)
// ---------------------------------------------------------------------------
__global__ __launch_bounds__(128)
void ct_k(const float* __restrict__ att, const float* __restrict__ sent,
          float* __restrict__ out) {
    __shared__ float al[4][DK];
    __shared__ float bsm[4];

    const int tid = threadIdx.x;
    const int b   = blockIdx.y;
    const int t0  = blockIdx.x * 4;
    const float* out_alpha = out + OUT_ALPHA_OFF;
    const float* out_beta  = out + OUT_BETA_OFF;

    for (int i = tid; i < 4 * DK; i += 128) {
        int t = i / DK, k = i - t * DK;
        al[t][k] = out_alpha[(b * DT + t0 + t) * DK + k];
    }
    if (tid < 4) bsm[tid] = out_beta[b * DT + t0 + tid];
    __syncthreads();

    const int w = tid >> 5, lane = tid & 31;
    const int h = w * 128 + lane * 4;

    float4 acc[4];
#pragma unroll
    for (int i = 0; i < 4; i++) acc[i] = make_float4(0.f, 0.f, 0.f, 0.f);

    const float* ap = att + (b * DK) * DH + h;
#pragma unroll 4
    for (int k = 0; k < DK; k++) {
        float4 af = *(const float4*)(ap + k * DH);
#pragma unroll
        for (int tt = 0; tt < 4; tt++) {
            float a = al[tt][k];
            acc[tt].x = fmaf(a, af.x, acc[tt].x);
            acc[tt].y = fmaf(a, af.y, acc[tt].y);
            acc[tt].z = fmaf(a, af.z, acc[tt].z);
            acc[tt].w = fmaf(a, af.w, acc[tt].w);
        }
    }

#pragma unroll
    for (int tt = 0; tt < 4; tt++) {
        const int off = (b * DT + t0 + tt) * DH + h;
        float4 s = *(const float4*)(sent + off);
        float bt = bsm[tt];
        float4 r;
        r.x = fmaf(bt, s.x - acc[tt].x, acc[tt].x);
        r.y = fmaf(bt, s.y - acc[tt].y, acc[tt].y);
        r.z = fmaf(bt, s.z - acc[tt].z, acc[tt].z);
        r.w = fmaf(bt, s.w - acc[tt].w, acc[tt].w);
        *(float4*)(out + off) = r;
    }
}

// ---------------------------------------------------------------------------
extern "C" void kernel_launch(void* const* d_in, const int* in_sizes, int n_in,
                              void* d_out, int out_size) {
    const float* att = (const float*)d_in[0];
    const float* hid = (const float*)d_in[1];
    const float* sen = (const float*)d_in[2];
    const float* Wv  = (const float*)d_in[3];
    const float* Wg  = (const float*)d_in[4];
    const float* Ws  = (const float*)d_in[5];
    const float* wh  = (const float*)d_in[6];
    float* out = (float*)d_out;

    static int smem_set = 0;
    if (!smem_set) {
        cudaFuncSetAttribute(gemm_mma,
                             cudaFuncAttributeMaxDynamicSharedMemorySize,
                             2 * BUF_B);
        smem_set = 1;
    }

    conv_w<<<dim3(16, 16, 3), dim3(32, 8)>>>(Wv, Wg, Ws);
    gemm_mma<<<260, 256, 2 * BUF_B>>>(att, hid, sen);
    z_kernel<<<dim3(2, 128), 256>>>(wh);
    softmax_k<<<128, 256>>>(wh, out);
    ct_k<<<dim3(8, 32), 128>>>(att, sen, out);
}

// round 6
// speedup vs baseline: 2.1229x; 1.0979x over previous
#include <cuda_runtime.h>
#include <cuda_bf16.h>
#include <cstdint>

// Problem dims (fixed by the dataset)
#define DB 32
#define DT 32
#define DK 196
#define DH 512
#define DA 512

#define OUT_ALPHA_OFF (DB*DT*DH)            // 524288
#define OUT_BETA_OFF  (DB*DT*DH + DB*DT*DK) // 724992

// Scratch (allocation-free rule: __device__ globals)
__device__ float g_cv[DB*DK*DA];   // att_feats @ Wv   (6272 x 512)
__device__ float g_cg[DB*DT*DA];   // hiddens   @ Wg   (1024 x 512)
__device__ float g_cs[DB*DT*DA];   // sentinel  @ Ws   (1024 x 512)
__device__ float g_zt[DB*DT*DK];   // logits           (1024 x 196)
__device__ __nv_bfloat16 g_wt_hi[3*512*512];   // W^T hi, [wsel][n][k]
__device__ __nv_bfloat16 g_wt_lo[3*512*512];   // W^T lo
__device__ __nv_bfloat16 g_a_hi[8320*512];     // A hi: att|hid|sen rows
__device__ __nv_bfloat16 g_a_lo[8320*512];     // A lo

// ---------------------------------------------------------------------------
// helpers
// ---------------------------------------------------------------------------
__device__ __forceinline__ uint32_t smem_to_u32(const void* p) {
    uint32_t a;
    asm("{ .reg .u64 t; cvta.to.shared.u64 t, %1; cvt.u32.u64 %0, t; }"
        : "=r"(a) : "l"(p));
    return a;
}
#define SWZ(o) ((o) ^ (((o) >> 3) & 0x70))

__device__ __forceinline__ void ldsm_x4(uint32_t* r, uint32_t addr) {
    asm volatile("ldmatrix.sync.aligned.m8n8.x4.shared.b16 {%0,%1,%2,%3}, [%4];"
        : "=r"(r[0]), "=r"(r[1]), "=r"(r[2]), "=r"(r[3]) : "r"(addr));
}
__device__ __forceinline__ void mma16816(float* c, const uint32_t* a,
                                         const uint32_t* b) {
    asm volatile(
        "mma.sync.aligned.m16n8k16.row.col.f32.bf16.bf16.f32 "
        "{%0,%1,%2,%3}, {%4,%5,%6,%7}, {%8,%9}, {%0,%1,%2,%3};"
        : "+f"(c[0]), "+f"(c[1]), "+f"(c[2]), "+f"(c[3])
        : "r"(a[0]), "r"(a[1]), "r"(a[2]), "r"(a[3]), "r"(b[0]), "r"(b[1]));
}
__device__ __forceinline__ void cpa16(uint32_t dst, const __nv_bfloat16* src) {
    asm volatile("cp.async.cg.shared.global [%0], [%1], 16;"
        :: "r"(dst), "l"(src));
}
__device__ __forceinline__ void fma2(unsigned long long& c,
                                     unsigned long long a,
                                     unsigned long long b) {
    asm("fma.rn.f32x2 %0, %1, %2, %0;" : "+l"(c) : "l"(a), "l"(b));
}
__device__ __forceinline__ unsigned long long pack2(float a, float b) {
    unsigned long long d;
    asm("mov.b64 %0, {%1, %2};" : "=l"(d) : "f"(a), "f"(b));
    return d;
}
__device__ __forceinline__ float lo2(unsigned long long v) {
    float a; unsigned hi;
    asm("mov.b64 {%0, %1}, %2;" : "=f"(a), "=r"(hi) : "l"(v));
    return a;
}
__device__ __forceinline__ float hi2(unsigned long long v) {
    unsigned lo; float b;
    asm("mov.b64 {%0, %1}, %2;" : "=r"(lo), "=f"(b) : "l"(v));
    return b;
}
__device__ __forceinline__ float tanh_approx(float x) {
    float y;
    asm("tanh.approx.f32 %0, %1;" : "=f"(y) : "f"(x));
    return y;
}

// ---------------------------------------------------------------------------
// W transpose + bf16 hi/lo split:  g_wt_{hi,lo}[wsel][n][k] = split(W[k][n])
// ---------------------------------------------------------------------------
__global__ void conv_w(const float* __restrict__ Wv,
                       const float* __restrict__ Wg,
                       const float* __restrict__ Ws) {
    __shared__ float tile[32][33];
    const int wsel = blockIdx.z;
    const float* W = (wsel == 0) ? Wv : ((wsel == 1) ? Wg : Ws);
    const int kb = blockIdx.y * 32, nb = blockIdx.x * 32;
    const int tx = threadIdx.x, ty = threadIdx.y;   // 32 x 8

#pragma unroll
    for (int i = 0; i < 32; i += 8)
        tile[ty + i][tx] = W[(kb + ty + i) * 512 + nb + tx];
    __syncthreads();

    __nv_bfloat16* oh = g_wt_hi + wsel * 262144;
    __nv_bfloat16* ol = g_wt_lo + wsel * 262144;
#pragma unroll
    for (int i = 0; i < 32; i += 8) {
        float v = tile[tx][ty + i];
        __nv_bfloat16 h = __float2bfloat16(v);
        oh[(nb + ty + i) * 512 + kb + tx] = h;
        ol[(nb + ty + i) * 512 + kb + tx] = __float2bfloat16(v - __bfloat162float(h));
    }
}

// ---------------------------------------------------------------------------
// A hi/lo split: rows 0..6271 att, 6272..7295 hid, 7296..8319 sen
// ---------------------------------------------------------------------------
__global__ __launch_bounds__(256)
void conv_a(const float* __restrict__ att, const float* __restrict__ hid,
            const float* __restrict__ sen) {
    const int idx = blockIdx.x * 256 + threadIdx.x;   // float4 index
    const int row = idx >> 7;
    const int c4  = idx & 127;
    const float* src; int lrow;
    if (row < 6272)      { src = att; lrow = row; }
    else if (row < 7296) { src = hid; lrow = row - 6272; }
    else                 { src = sen; lrow = row - 7296; }
    float4 v = *(const float4*)(src + lrow * 512 + c4 * 4);
    __nv_bfloat162 h0, h1, l0, l1;
    h0.x = __float2bfloat16(v.x); h0.y = __float2bfloat16(v.y);
    h1.x = __float2bfloat16(v.z); h1.y = __float2bfloat16(v.w);
    l0.x = __float2bfloat16(v.x - __bfloat162float(h0.x));
    l0.y = __float2bfloat16(v.y - __bfloat162float(h0.y));
    l1.x = __float2bfloat16(v.z - __bfloat162float(h1.x));
    l1.y = __float2bfloat16(v.w - __bfloat162float(h1.y));
    __nv_bfloat162* dh = (__nv_bfloat162*)(g_a_hi + row * 512 + c4 * 4);
    __nv_bfloat162* dl = (__nv_bfloat162*)(g_a_lo + row * 512 + c4 * 4);
    dh[0] = h0; dh[1] = h1;
    dl[0] = l0; dl[1] = l1;
}

// ---------------------------------------------------------------------------
// Fused HMMA GEMM, v2: 512 threads (16 warps, 4/SMSP), warp tile 32x32,
// cp.async 3-stage pipeline (64KB/stage: AH|AL|BH|BL 16KB each).
// All operands pre-split bf16.  Split-bf16: C = Ah*Bh + Ah*Bl + Al*Bh.
// ---------------------------------------------------------------------------
#define STAGE_B 65536
#define GEMM_SMEM (3 * STAGE_B)

__global__ __launch_bounds__(512, 1)
void gemm_mma() {
    extern __shared__ __align__(1024) char smem[];
    const uint32_t sbase = smem_to_u32(smem);

    const int tid  = threadIdx.x;
    const int wid  = tid >> 5, lane = tid & 31;
    const int wm   = (wid & 3) * 32;    // warp m offset in tile
    const int wn   = (wid >> 2) * 32;   // warp n offset in tile

    // job decode: 260 = 196(cv) + 32(cg) + 32(cs)
    const int bid = blockIdx.x;
    float* Cg; int wsel, mt, nt, row_off;
    if (bid < 196)      { mt = bid >> 2; nt = bid & 3; Cg = g_cv; wsel = 0; row_off = 0; }
    else if (bid < 228) { int i = bid - 196; mt = i >> 2; nt = i & 3; Cg = g_cg; wsel = 1; row_off = 6272; }
    else                { int i = bid - 228; mt = i >> 2; nt = i & 3; Cg = g_cs; wsel = 2; row_off = 7296; }
    const int m0 = mt * 128, n0 = nt * 128;

    const __nv_bfloat16* AHg = g_a_hi + (row_off + m0) * 512;
    const __nv_bfloat16* ALg = g_a_lo + (row_off + m0) * 512;
    const __nv_bfloat16* BHg = g_wt_hi + wsel * 262144 + n0 * 512;
    const __nv_bfloat16* BLg = g_wt_lo + wsel * 262144 + n0 * 512;

    // loader mapping (per stage): 1024 16B-chunks per operand tile
    const int lrow0 = (tid * 2) >> 3, lch0 = (tid * 2) & 7;        // idx = tid*2? no:
    (void)lrow0; (void)lch0;

    float c[2][4][4];
#pragma unroll
    for (int i = 0; i < 2; i++)
#pragma unroll
        for (int j = 0; j < 4; j++)
#pragma unroll
            for (int q = 0; q < 4; q++) c[i][j][q] = 0.f;

    // issue one stage of cp.async (8 x 16B per thread)
    auto issue = [&](int chunk, int st) {
        const int k0 = chunk * 64;
        const uint32_t sb = sbase + st * STAGE_B;
#pragma unroll
        for (int j = 0; j < 2; j++) {
            const int idx = tid + j * 512;       // 0..1023
            const int row = idx >> 3, ch = idx & 7;
            const uint32_t doff = SWZ((uint32_t)(row * 128 + ch * 16));
            const int soff = row * 512 + k0 + ch * 8;
            cpa16(sb + doff,          AHg + soff);
            cpa16(sb + 16384 + doff,  ALg + soff);
            cpa16(sb + 32768 + doff,  BHg + soff);
            cpa16(sb + 49152 + doff,  BLg + soff);
        }
        asm volatile("cp.async.commit_group;" ::: "memory");
    };

    issue(0, 0);
    issue(1, 1);

    for (int i = 0; i < 8; i++) {
        if (i + 2 < 8) issue(i + 2, (i + 2) % 3);
        if (i < 6)      asm volatile("cp.async.wait_group 2;" ::: "memory");
        else if (i == 6) asm volatile("cp.async.wait_group 1;" ::: "memory");
        else             asm volatile("cp.async.wait_group 0;" ::: "memory");
        __syncthreads();

        const uint32_t AH = sbase + (i % 3) * STAGE_B;
        const uint32_t AL = AH + 16384, BH = AH + 32768, BL = AH + 49152;
#pragma unroll
        for (int ks = 0; ks < 4; ks++) {
            const uint32_t kbA = (uint32_t)((ks * 16 + (lane >> 4) * 8) * 2);
            uint32_t ah[2][4], al[2][4];
#pragma unroll
            for (int mtile = 0; mtile < 2; mtile++) {
                uint32_t rowb = (uint32_t)((wm + mtile * 16 + (lane & 15)) * 128);
                uint32_t off  = SWZ(rowb + kbA);
                ldsm_x4(ah[mtile], AH + off);
                ldsm_x4(al[mtile], AL + off);
            }
            const uint32_t kbB = (uint32_t)((ks * 16 + ((lane >> 3) & 1) * 8) * 2);
            uint32_t bh[2][4], bl[2][4];
#pragma unroll
            for (int p = 0; p < 2; p++) {
                uint32_t nrow = (uint32_t)(wn + p * 16 + (lane & 7) +
                                           ((lane >> 4) & 1) * 8);
                uint32_t off = SWZ(nrow * 128 + kbB);
                ldsm_x4(bh[p], BH + off);
                ldsm_x4(bl[p], BL + off);
            }
#pragma unroll
            for (int mtile = 0; mtile < 2; mtile++) {
#pragma unroll
                for (int p = 0; p < 2; p++) {
#pragma unroll
                    for (int h = 0; h < 2; h++) {
                        float* cc = c[mtile][p * 2 + h];
                        mma16816(cc, ah[mtile], &bh[p][2 * h]);
                        mma16816(cc, ah[mtile], &bl[p][2 * h]);
                        mma16816(cc, al[mtile], &bh[p][2 * h]);
                    }
                }
            }
        }
        __syncthreads();
    }

    // epilogue
    const int r0 = lane >> 2, col = (lane & 3) * 2;
#pragma unroll
    for (int mtile = 0; mtile < 2; mtile++) {
#pragma unroll
        for (int ntl = 0; ntl < 4; ntl++) {
            float* cc = c[mtile][ntl];
            float* base = Cg + (m0 + wm + mtile * 16 + r0) * 512
                             + n0 + wn + ntl * 8 + col;
            *(float2*)(base)           = make_float2(cc[0], cc[1]);
            *(float2*)(base + 8 * 512) = make_float2(cc[2], cc[3]);
        }
    }
}

// ---------------------------------------------------------------------------
// z_t[b,t,k] = sum_a tanh(cv[b,k,a] + cg[b,t,a]) * wh[a]
// ---------------------------------------------------------------------------
__global__ __launch_bounds__(256, 3)
void z_kernel(const float* __restrict__ wh) {
    __shared__ __align__(16) float cgs[8][512];
    __shared__ __align__(16) float whs[512];

    const int tid = threadIdx.x;
    const int b   = blockIdx.y >> 2;
    const int t0  = (blockIdx.y & 3) * 8;
    const int klo = blockIdx.x * 98;
    const int khi = klo + 98;

    const float* cgbase = g_cg + (b * DT + t0) * DA;
    for (int i = tid; i < 8 * 512; i += 256) ((float*)cgs)[i] = cgbase[i];
    for (int i = tid; i < 512; i += 256) whs[i] = wh[i];
    __syncthreads();

    const int w = tid >> 5, lane = tid & 31;

    for (int k = klo + w; k < khi; k += 8) {
        const float4* cvp = (const float4*)(g_cv + (b * DK + k) * DA);

        unsigned long long acc[8];
#pragma unroll
        for (int tt = 0; tt < 8; tt++) acc[tt] = 0ull;

#pragma unroll
        for (int j = 0; j < 4; j++) {
            const int i = lane + j * 32;
            float4 v = cvp[i];
            ulonglong2 whv = ((const ulonglong2*)whs)[i];
#pragma unroll
            for (int tt = 0; tt < 8; tt++) {
                float4 cvec = ((const float4*)cgs[tt])[i];
                unsigned long long p0 = pack2(tanh_approx(v.x + cvec.x),
                                              tanh_approx(v.y + cvec.y));
                fma2(acc[tt], p0, whv.x);
                unsigned long long p1 = pack2(tanh_approx(v.z + cvec.z),
                                              tanh_approx(v.w + cvec.w));
                fma2(acc[tt], p1, whv.y);
            }
        }

#pragma unroll
        for (int tt = 0; tt < 8; tt++) {
            float s = lo2(acc[tt]) + hi2(acc[tt]);
            s += __shfl_xor_sync(0xffffffffu, s, 16);
            s += __shfl_xor_sync(0xffffffffu, s, 8);
            s += __shfl_xor_sync(0xffffffffu, s, 4);
            s += __shfl_xor_sync(0xffffffffu, s, 2);
            s += __shfl_xor_sync(0xffffffffu, s, 1);
            if (lane == 0) g_zt[(b * DT + t0 + tt) * DK + k] = s;
        }
    }
}

// ---------------------------------------------------------------------------
// Fused softmax + c_t + gate.  Block: (b, t0..t0+3), 128 threads (4 warps).
// Warp w: softmax for row t0+w (z_ext from cs+cg, alpha, beta), then all
// warps do c_t GEMV over float4 h-vectors and the sentinel gate.
// ---------------------------------------------------------------------------
__global__ __launch_bounds__(128)
void ct_k(const float* __restrict__ att, const float* __restrict__ sent,
          const float* __restrict__ wh, float* __restrict__ out) {
    __shared__ float al[4][DK];
    __shared__ float bsm[4];

    const int tid = threadIdx.x;
    const int b   = blockIdx.y;
    const int t0  = blockIdx.x * 4;
    float* out_alpha = out + OUT_ALPHA_OFF;
    float* out_beta  = out + OUT_BETA_OFF;

    const int w = tid >> 5, lane = tid & 31;

    // --- per-warp softmax for row (b, t0+w) ---
    {
        const int row = b * DT + t0 + w;
        const float* cs = g_cs + row * DA;
        const float* cg = g_cg + row * DA;
        float ze = 0.f;
#pragma unroll
        for (int j = 0; j < 16; j++) {
            int a = lane + j * 32;
            ze = fmaf(tanh_approx(cs[a] + cg[a]), wh[a], ze);
        }
        ze += __shfl_xor_sync(0xffffffffu, ze, 16);
        ze += __shfl_xor_sync(0xffffffffu, ze, 8);
        ze += __shfl_xor_sync(0xffffffffu, ze, 4);
        ze += __shfl_xor_sync(0xffffffffu, ze, 2);
        ze += __shfl_xor_sync(0xffffffffu, ze, 1);

        const float* zr = g_zt + row * DK;
        float zv[7];
        float m = -1e30f;
#pragma unroll
        for (int j = 0; j < 7; j++) {
            int k = lane + j * 32;
            zv[j] = (k < DK) ? zr[k] : -1e30f;
            m = fmaxf(m, zv[j]);
        }
        m = fmaxf(m, __shfl_xor_sync(0xffffffffu, m, 16));
        m = fmaxf(m, __shfl_xor_sync(0xffffffffu, m, 8));
        m = fmaxf(m, __shfl_xor_sync(0xffffffffu, m, 4));
        m = fmaxf(m, __shfl_xor_sync(0xffffffffu, m, 2));
        m = fmaxf(m, __shfl_xor_sync(0xffffffffu, m, 1));

        float p[7];
        float S = 0.f;
#pragma unroll
        for (int j = 0; j < 7; j++) {
            p[j] = __expf(zv[j] - m);
            S += p[j];
        }
        S += __shfl_xor_sync(0xffffffffu, S, 16);
        S += __shfl_xor_sync(0xffffffffu, S, 8);
        S += __shfl_xor_sync(0xffffffffu, S, 4);
        S += __shfl_xor_sync(0xffffffffu, S, 2);
        S += __shfl_xor_sync(0xffffffffu, S, 1);

        float invS = 1.0f / S;
#pragma unroll
        for (int j = 0; j < 7; j++) {
            int k = lane + j * 32;
            if (k < DK) {
                float a = p[j] * invS;
                out_alpha[row * DK + k] = a;
                al[w][k] = a;
            }
        }

        float m2  = fmaxf(m, ze);
        float eb  = __expf(ze - m2);
        float den = S * __expf(m - m2) + eb;
        if (lane == 0) {
            float beta = eb / den;
            out_beta[row] = beta;
            bsm[w] = beta;
        }
    }
    __syncthreads();

    // --- c_t GEMV + gate ---
    const int h = w * 128 + lane * 4;

    float4 acc[4];
#pragma unroll
    for (int i = 0; i < 4; i++) acc[i] = make_float4(0.f, 0.f, 0.f, 0.f);

    const float* ap = att + (b * DK) * DH + h;
#pragma unroll 4
    for (int k = 0; k < DK; k++) {
        float4 af = *(const float4*)(ap + k * DH);
#pragma unroll
        for (int tt = 0; tt < 4; tt++) {
            float a = al[tt][k];
            acc[tt].x = fmaf(a, af.x, acc[tt].x);
            acc[tt].y = fmaf(a, af.y, acc[tt].y);
            acc[tt].z = fmaf(a, af.z, acc[tt].z);
            acc[tt].w = fmaf(a, af.w, acc[tt].w);
        }
    }

#pragma unroll
    for (int tt = 0; tt < 4; tt++) {
        const int off = (b * DT + t0 + tt) * DH + h;
        float4 s = *(const float4*)(sent + off);
        float bt = bsm[tt];
        float4 r;
        r.x = fmaf(bt, s.x - acc[tt].x, acc[tt].x);
        r.y = fmaf(bt, s.y - acc[tt].y, acc[tt].y);
        r.z = fmaf(bt, s.z - acc[tt].z, acc[tt].z);
        r.w = fmaf(bt, s.w - acc[tt].w, acc[tt].w);
        *(float4*)(out + off) = r;
    }
}

// ---------------------------------------------------------------------------
extern "C" void kernel_launch(void* const* d_in, const int* in_sizes, int n_in,
                              void* d_out, int out_size) {
    const float* att = (const float*)d_in[0];
    const float* hid = (const float*)d_in[1];
    const float* sen = (const float*)d_in[2];
    const float* Wv  = (const float*)d_in[3];
    const float* Wg  = (const float*)d_in[4];
    const float* Ws  = (const float*)d_in[5];
    const float* wh  = (const float*)d_in[6];
    float* out = (float*)d_out;

    static int smem_set = 0;
    if (!smem_set) {
        cudaFuncSetAttribute(gemm_mma,
                             cudaFuncAttributeMaxDynamicSharedMemorySize,
                             GEMM_SMEM);
        smem_set = 1;
    }

    conv_w<<<dim3(16, 16, 3), dim3(32, 8)>>>(Wv, Wg, Ws);
    conv_a<<<4160, 256>>>(att, hid, sen);
    gemm_mma<<<260, 512, GEMM_SMEM>>>();
    z_kernel<<<dim3(2, 128), 256>>>(wh);
    ct_k<<<dim3(8, 32), 128>>>(att, sen, wh, out);
}